// round 2
// baseline (speedup 1.0000x reference)
#include <cuda_runtime.h>

#define DIMF 1536
#define SEQ  1560
#define LKV  4680
#define NH   12
#define HD   128

typedef unsigned long long u64;

__device__ __forceinline__ u64 pack2(float x, float y) {
    u64 r; asm("mov.b64 %0,{%1,%2};" : "=l"(r) : "f"(x), "f"(y)); return r;
}
__device__ __forceinline__ void ffma2(u64& d, u64 a, u64 b) {
    asm("fma.rn.f32x2 %0,%1,%2,%0;" : "+l"(d) : "l"(a), "l"(b));
}
__device__ __forceinline__ u64 fmul2(u64 a, u64 b) {
    u64 d; asm("mul.rn.f32x2 %0,%1,%2;" : "=l"(d) : "l"(a), "l"(b)); return d;
}
__device__ __forceinline__ float2 unpack2(u64 v) {
    float2 r; asm("mov.b64 {%0,%1},%2;" : "=f"(r.x), "=f"(r.y) : "l"(v)); return r;
}

// scratch (allocation-free: device globals)
__device__ float g_q[SEQ * DIMF];
__device__ float g_k[SEQ * DIMF];
__device__ float g_v[SEQ * DIMF];
__device__ float g_o[SEQ * DIMF];

// ---------------------------------------------------------------------------
// GEMM: out[M,1536] = A[M,1536] @ W[1536,1536] + bias, fp32 with f32x2 FMA.
// 64x64 tile, BK=16, 256 threads, 4x4 per thread (2x f32x2 along N).
// ---------------------------------------------------------------------------
__global__ __launch_bounds__(256) void gemm_bias(
    const float* __restrict__ A, const float* __restrict__ W,
    const float* __restrict__ bias, float* __restrict__ out, int M)
{
    __shared__ float As[16][64];
    __shared__ float Bs[16][64];
    const int bm = blockIdx.x * 64;
    const int bn = blockIdx.y * 64;
    const int tid = threadIdx.x;
    const int tx = tid & 15, ty = tid >> 4;
    const int m0 = ty * 4, n0 = tx * 4;

    u64 acc[4][2];
#pragma unroll
    for (int i = 0; i < 4; i++) { acc[i][0] = 0ull; acc[i][1] = 0ull; }

    const int lm = tid >> 2;          // A row in tile (0..63)
    const int lk = (tid & 3) * 4;     // A k offset (float4)
    const int bkr = tid >> 4;         // B k row (0..15)
    const int bn4 = (tid & 15) * 4;   // B n offset

    for (int k0 = 0; k0 < DIMF; k0 += 16) {
        float4 a4 = make_float4(0.f, 0.f, 0.f, 0.f);
        if (bm + lm < M) a4 = *(const float4*)(A + (size_t)(bm + lm) * DIMF + k0 + lk);
        float4 b4 = *(const float4*)(W + (size_t)(k0 + bkr) * DIMF + bn + bn4);
        As[lk][lm] = a4.x; As[lk + 1][lm] = a4.y; As[lk + 2][lm] = a4.z; As[lk + 3][lm] = a4.w;
        *(float4*)&Bs[bkr][bn4] = b4;
        __syncthreads();
#pragma unroll
        for (int kk = 0; kk < 16; kk++) {
            float4 av = *(const float4*)&As[kk][m0];
            u64 b0 = *(const u64*)&Bs[kk][n0];
            u64 b1 = *(const u64*)&Bs[kk][n0 + 2];
            u64 a0 = pack2(av.x, av.x);
            u64 a1 = pack2(av.y, av.y);
            u64 a2 = pack2(av.z, av.z);
            u64 a3 = pack2(av.w, av.w);
            ffma2(acc[0][0], a0, b0); ffma2(acc[0][1], a0, b1);
            ffma2(acc[1][0], a1, b0); ffma2(acc[1][1], a1, b1);
            ffma2(acc[2][0], a2, b0); ffma2(acc[2][1], a2, b1);
            ffma2(acc[3][0], a3, b0); ffma2(acc[3][1], a3, b1);
        }
        __syncthreads();
    }

    float4 bv = *(const float4*)(bias + bn + n0);
#pragma unroll
    for (int i = 0; i < 4; i++) {
        int gm = bm + m0 + i;
        if (gm < M) {
            float2 lo = unpack2(acc[i][0]);
            float2 hi = unpack2(acc[i][1]);
            *(float4*)(out + (size_t)gm * DIMF + bn + n0) =
                make_float4(lo.x + bv.x, lo.y + bv.y, hi.x + bv.z, hi.y + bv.w);
        }
    }
}

// ---------------------------------------------------------------------------
// RMSNorm (over full 1536) + RoPE. One block per (token, q/k).
// f=1,h=30,w=52,start_frame=3; c0=22,c1=21 (static for this problem).
// ---------------------------------------------------------------------------
__global__ __launch_bounds__(256) void rmsrope(
    float* __restrict__ qbuf, float* __restrict__ kbuf,
    const float* __restrict__ gq, const float* __restrict__ gk,
    const float* __restrict__ fre, const float* __restrict__ fim)
{
    const int t = blockIdx.x;
    float* row = (blockIdx.y == 0 ? qbuf : kbuf) + (size_t)t * DIMF;
    const float* g = blockIdx.y == 0 ? gq : gk;
    const int tid = threadIdx.x;

    float ss = 0.f;
#pragma unroll
    for (int u = 0; u < 6; u++) { float v = row[tid + u * 256]; ss += v * v; }
#pragma unroll
    for (int off = 16; off; off >>= 1) ss += __shfl_xor_sync(0xffffffffu, ss, off);
    __shared__ float red[8];
    if ((tid & 31) == 0) red[tid >> 5] = ss;
    __syncthreads();
    float tot = red[0] + red[1] + red[2] + red[3] + red[4] + red[5] + red[6] + red[7];
    float r = rsqrtf(tot * (1.f / 1536.f) + 1e-6f);

    const int wi = t % 52;
    const int hi = t / 52;   // < 30
#pragma unroll
    for (int u = 0; u < 3; u++) {
        int p = tid + u * 256;      // pair index 0..767
        int hh = p >> 6, c = p & 63;
        int d0 = hh * 128 + 2 * c;
        int frow = (c < 22) ? 3 : (c < 43) ? hi : wi;
        float cr = fre[frow * 64 + c], ci = fim[frow * 64 + c];
        float v0 = row[d0] * r * g[d0];
        float v1 = row[d0 + 1] * r * g[d0 + 1];
        row[d0]     = v0 * cr - v1 * ci;
        row[d0 + 1] = v0 * ci + v1 * cr;
    }
}

// ---------------------------------------------------------------------------
// Flash attention, fp32. Block = (64 queries, 1 head). 256 threads (16x16).
// Logical KV j: [0,1560)->cache[j], [1560,3120)->cache[j+1560], else new[j-3120].
// Dyn smem: Qs[d][qi] 32KB | KV tile 32KB (K as [d][kj], then V as [kj][d]) |
// Ps[qi][65] 16.25KB  => 82176 B, 2 blocks/SM.
// ---------------------------------------------------------------------------
__global__ __launch_bounds__(256, 2) void attn(
    const float* __restrict__ q, const float* __restrict__ knew,
    const float* __restrict__ vnew, const float* __restrict__ ck,
    const float* __restrict__ cv, float* __restrict__ out)
{
    extern __shared__ float smem[];
    float* Qs  = smem;            // 128*64
    float* KVs = smem + 8192;     // 64*128
    float* Ps  = smem + 16384;    // 64*65

    const int h  = blockIdx.y;
    const int q0 = blockIdx.x * 64;
    const int tid = threadIdx.x;
    const int tx = tid & 15, ty = tid >> 4;
    const int m0 = ty * 4, n0 = tx * 4;

    // Q tile, transposed + pre-scaled
    {
        const int qi = tid >> 2;
        const int dd = (tid & 3) * 32;
        const bool ok = (q0 + qi) < SEQ;
        const float* src = q + (size_t)(q0 + qi) * DIMF + h * HD + dd;
        const float sc = 0.08838834764831845f; // 1/sqrt(128)
#pragma unroll
        for (int u = 0; u < 8; u++) {
            float4 v = ok ? *(const float4*)(src + u * 4) : make_float4(0, 0, 0, 0);
            int d = dd + u * 4;
            Qs[d * 64 + qi] = v.x * sc; Qs[(d + 1) * 64 + qi] = v.y * sc;
            Qs[(d + 2) * 64 + qi] = v.z * sc; Qs[(d + 3) * 64 + qi] = v.w * sc;
        }
    }

    float m_i[4] = { -1e30f, -1e30f, -1e30f, -1e30f };
    float l_i[4] = { 0.f, 0.f, 0.f, 0.f };
    u64 o2[4][4];
#pragma unroll
    for (int i = 0; i < 4; i++)
#pragma unroll
        for (int j = 0; j < 4; j++) o2[i][j] = 0ull;

    __syncthreads();

    const int kvi = tid >> 2;        // key row in tile
    const int kvd = (tid & 3) * 32;  // d offset

    for (int kt = 0; kt < LKV; kt += 64) {
        // --- K tile, transposed [d][kj] ---
        {
            int j = kt + kvi;
            const float* src = (j < 1560) ? ck + ((size_t)j * NH + h) * HD
                             : (j < 3120) ? ck + ((size_t)(j + 1560) * NH + h) * HD
                             : knew + (size_t)(j - 3120) * DIMF + h * HD;
#pragma unroll
            for (int u = 0; u < 8; u++) {
                float4 v = (j < LKV) ? *(const float4*)(src + kvd + u * 4)
                                     : make_float4(0, 0, 0, 0);
                int d = kvd + u * 4;
                KVs[d * 64 + kvi] = v.x; KVs[(d + 1) * 64 + kvi] = v.y;
                KVs[(d + 2) * 64 + kvi] = v.z; KVs[(d + 3) * 64 + kvi] = v.w;
            }
        }
        __syncthreads();

        // --- S = Q K^T (outer-product over d) ---
        u64 s2[4][2];
#pragma unroll
        for (int i = 0; i < 4; i++) { s2[i][0] = 0ull; s2[i][1] = 0ull; }
#pragma unroll 4
        for (int d = 0; d < 128; d++) {
            float4 av = *(const float4*)&Qs[d * 64 + m0];
            u64 b0 = *(const u64*)&KVs[d * 64 + n0];
            u64 b1 = *(const u64*)&KVs[d * 64 + n0 + 2];
            u64 a0 = pack2(av.x, av.x), a1 = pack2(av.y, av.y);
            u64 a2 = pack2(av.z, av.z), a3 = pack2(av.w, av.w);
            ffma2(s2[0][0], a0, b0); ffma2(s2[0][1], a0, b1);
            ffma2(s2[1][0], a1, b0); ffma2(s2[1][1], a1, b1);
            ffma2(s2[2][0], a2, b0); ffma2(s2[2][1], a2, b1);
            ffma2(s2[3][0], a3, b0); ffma2(s2[3][1], a3, b1);
        }

        float sv[4][4];
#pragma unroll
        for (int i = 0; i < 4; i++) {
            float2 lo = unpack2(s2[i][0]); float2 hi = unpack2(s2[i][1]);
            sv[i][0] = lo.x; sv[i][1] = lo.y; sv[i][2] = hi.x; sv[i][3] = hi.y;
        }
        if (kt + 64 > LKV) {
#pragma unroll
            for (int j = 0; j < 4; j++)
                if (kt + n0 + j >= LKV) {
#pragma unroll
                    for (int i = 0; i < 4; i++) sv[i][j] = -1e30f;
                }
        }

        // --- online softmax (rows live in 16-lane half-warps) ---
#pragma unroll
        for (int i = 0; i < 4; i++) {
            float mx = fmaxf(fmaxf(sv[i][0], sv[i][1]), fmaxf(sv[i][2], sv[i][3]));
            mx = fmaxf(mx, __shfl_xor_sync(0xffffffffu, mx, 1));
            mx = fmaxf(mx, __shfl_xor_sync(0xffffffffu, mx, 2));
            mx = fmaxf(mx, __shfl_xor_sync(0xffffffffu, mx, 4));
            mx = fmaxf(mx, __shfl_xor_sync(0xffffffffu, mx, 8));
            float mnew = fmaxf(m_i[i], mx);
            float alpha = __expf(m_i[i] - mnew);
            float p0 = __expf(sv[i][0] - mnew), p1 = __expf(sv[i][1] - mnew);
            float p2 = __expf(sv[i][2] - mnew), p3 = __expf(sv[i][3] - mnew);
            float rs = p0 + p1 + p2 + p3;
            rs += __shfl_xor_sync(0xffffffffu, rs, 1);
            rs += __shfl_xor_sync(0xffffffffu, rs, 2);
            rs += __shfl_xor_sync(0xffffffffu, rs, 4);
            rs += __shfl_xor_sync(0xffffffffu, rs, 8);
            l_i[i] = l_i[i] * alpha + rs;
            m_i[i] = mnew;
            Ps[(m0 + i) * 65 + n0]     = p0; Ps[(m0 + i) * 65 + n0 + 1] = p1;
            Ps[(m0 + i) * 65 + n0 + 2] = p2; Ps[(m0 + i) * 65 + n0 + 3] = p3;
            u64 al2 = pack2(alpha, alpha);
            o2[i][0] = fmul2(o2[i][0], al2); o2[i][1] = fmul2(o2[i][1], al2);
            o2[i][2] = fmul2(o2[i][2], al2); o2[i][3] = fmul2(o2[i][3], al2);
        }
        __syncthreads();

        // --- V tile [kj][d] (reuses K buffer) ---
        {
            int j = kt + kvi;
            const float* src = (j < 1560) ? cv + ((size_t)j * NH + h) * HD
                             : (j < 3120) ? cv + ((size_t)(j + 1560) * NH + h) * HD
                             : vnew + (size_t)(j - 3120) * DIMF + h * HD;
#pragma unroll
            for (int u = 0; u < 8; u++) {
                float4 v = (j < LKV) ? *(const float4*)(src + kvd + u * 4)
                                     : make_float4(0, 0, 0, 0);
                *(float4*)&KVs[kvi * 128 + kvd + u * 4] = v;
            }
        }
        __syncthreads();

        // --- O += P V : thread owns d = tx*4..+3 and 64+tx*4..+3 ---
        const int dlo = tx * 4;
#pragma unroll 4
        for (int kj = 0; kj < 64; kj++) {
            u64 v0 = *(const u64*)&KVs[kj * 128 + dlo];
            u64 v1 = *(const u64*)&KVs[kj * 128 + dlo + 2];
            u64 v2 = *(const u64*)&KVs[kj * 128 + dlo + 64];
            u64 v3 = *(const u64*)&KVs[kj * 128 + dlo + 66];
#pragma unroll
            for (int i = 0; i < 4; i++) {
                float pv = Ps[(m0 + i) * 65 + kj];
                u64 pp = pack2(pv, pv);
                ffma2(o2[i][0], pp, v0); ffma2(o2[i][1], pp, v1);
                ffma2(o2[i][2], pp, v2); ffma2(o2[i][3], pp, v3);
            }
        }
        __syncthreads();
    }

    // epilogue
#pragma unroll
    for (int i = 0; i < 4; i++) {
        int gq2 = q0 + m0 + i;
        if (gq2 < SEQ) {
            float inv = 1.f / l_i[i];
            float2 a = unpack2(o2[i][0]), b = unpack2(o2[i][1]);
            float2 c = unpack2(o2[i][2]), d = unpack2(o2[i][3]);
            float* dst = out + (size_t)gq2 * DIMF + h * HD;
            *(float4*)(dst + tx * 4)      = make_float4(a.x * inv, a.y * inv, b.x * inv, b.y * inv);
            *(float4*)(dst + 64 + tx * 4) = make_float4(c.x * inv, c.y * inv, d.x * inv, d.y * inv);
        }
    }
}

// ---------------------------------------------------------------------------
extern "C" void kernel_launch(void* const* d_in, const int* in_sizes, int n_in,
                              void* d_out, int out_size)
{
    (void)in_sizes; (void)n_in; (void)out_size;
    const float* x   = (const float*)d_in[0];
    const float* ck  = (const float*)d_in[1];
    const float* cv  = (const float*)d_in[2];
    const float* fre = (const float*)d_in[3];
    const float* fim = (const float*)d_in[4];
    const float* wq  = (const float*)d_in[5];
    const float* bq  = (const float*)d_in[6];
    const float* wk  = (const float*)d_in[7];
    const float* bk  = (const float*)d_in[8];
    const float* wv  = (const float*)d_in[9];
    const float* bv  = (const float*)d_in[10];
    const float* wo  = (const float*)d_in[11];
    const float* bo  = (const float*)d_in[12];
    const float* gq  = (const float*)d_in[13];
    const float* gk  = (const float*)d_in[14];
    float* out = (float*)d_out;

    float *q, *k, *v, *o;
    cudaGetSymbolAddress((void**)&q, g_q);
    cudaGetSymbolAddress((void**)&k, g_k);
    cudaGetSymbolAddress((void**)&v, g_v);
    cudaGetSymbolAddress((void**)&o, g_o);

    const int attn_smem = (8192 + 8192 + 64 * 65) * 4;
    cudaFuncSetAttribute(attn, cudaFuncAttributeMaxDynamicSharedMemorySize, attn_smem);

    dim3 gg(25, 24);
    gemm_bias<<<gg, 256>>>(x, wq, bq, q, SEQ);
    gemm_bias<<<gg, 256>>>(x, wk, bk, k, SEQ);
    gemm_bias<<<gg, 256>>>(x, wv, bv, v, SEQ);
    rmsrope<<<dim3(SEQ, 2), 256>>>(q, k, gq, gk, fre, fim);
    attn<<<dim3(25, NH), 256, attn_smem>>>(q, k, v, ck, cv, o);
    gemm_bias<<<gg, 256>>>(o, wo, bo, out, SEQ);
}

// round 3
// speedup vs baseline: 2.0087x; 2.0087x over previous
#include <cuda_runtime.h>

#define DIMF 1536
#define SEQ  1560
#define LKV  4680
#define NH   12
#define HD   128

// scratch (allocation-free: device globals)
__device__ float g_q[SEQ * DIMF];
__device__ float g_k[SEQ * DIMF];
__device__ float g_v[SEQ * DIMF];
__device__ float g_o[SEQ * DIMF];

__device__ __forceinline__ unsigned f2tf(float f) {
    unsigned u; asm("cvt.rna.tf32.f32 %0,%1;" : "=r"(u) : "f"(f)); return u;
}

// D += A*B, m16n8k8 tf32, row.col
__device__ __forceinline__ void mma8(float* d, const unsigned* a, const unsigned* b) {
    asm volatile(
        "mma.sync.aligned.m16n8k8.row.col.f32.tf32.tf32.f32 "
        "{%0,%1,%2,%3},{%4,%5,%6,%7},{%8,%9},{%0,%1,%2,%3};"
        : "+f"(d[0]), "+f"(d[1]), "+f"(d[2]), "+f"(d[3])
        : "r"(a[0]), "r"(a[1]), "r"(a[2]), "r"(a[3]), "r"(b[0]), "r"(b[1]));
}

// ---------------------------------------------------------------------------
// GEMM: out[M,1536] = A[M,1536] @ W[1536,1536] + bias. tf32 mma, BM=BN=128,
// BK=16, 256 threads (8 warps 2x4), warp tile 64x32, register prefetch.
// ---------------------------------------------------------------------------
#define APAD 20
#define BPAD 136
__global__ __launch_bounds__(256) void gemm_tf32(
    const float* __restrict__ A, const float* __restrict__ W,
    const float* __restrict__ bias, float* __restrict__ out, int M)
{
    __shared__ unsigned As[128 * APAD];  // [m][k], pad 20 -> conflict-free a-frags
    __shared__ unsigned Bs[16 * BPAD];   // [k][n], pad 136 -> conflict-free b-frags
    const int bm = blockIdx.x * 128, bn = blockIdx.y * 128;
    const int tid = threadIdx.x, lane = tid & 31, warp = tid >> 5;
    const int wm = (warp >> 2) * 64, wn = (warp & 3) * 32;
    const int gi = lane >> 2, ti = lane & 3;

    float acc[4][4][4];
#pragma unroll
    for (int i = 0; i < 4; i++)
#pragma unroll
        for (int j = 0; j < 4; j++)
#pragma unroll
            for (int c = 0; c < 4; c++) acc[i][j][c] = 0.f;

    // loader index precompute: two float4 per thread for each of A,B
    const int fa0 = tid * 2, fa1 = tid * 2 + 1;

    float4 ra[2], rb[2];
    {
        int m0 = fa0 >> 2, kq0 = (fa0 & 3) * 4;
        int m1 = fa1 >> 2, kq1 = (fa1 & 3) * 4;
        ra[0] = (bm + m0 < M) ? *(const float4*)(A + (size_t)(bm + m0) * DIMF + kq0) : make_float4(0,0,0,0);
        ra[1] = (bm + m1 < M) ? *(const float4*)(A + (size_t)(bm + m1) * DIMF + kq1) : make_float4(0,0,0,0);
        int k0b = fa0 >> 5, n40 = (fa0 & 31) * 4;
        int k1b = fa1 >> 5, n41 = (fa1 & 31) * 4;
        rb[0] = *(const float4*)(W + (size_t)k0b * DIMF + bn + n40);
        rb[1] = *(const float4*)(W + (size_t)k1b * DIMF + bn + n41);
    }

    for (int k0 = 0; k0 < DIMF; k0 += 16) {
        // store staged tiles (convert to tf32)
        {
            int m0 = fa0 >> 2, kq0 = (fa0 & 3) * 4;
            int m1 = fa1 >> 2, kq1 = (fa1 & 3) * 4;
            uint4 u0 = { f2tf(ra[0].x), f2tf(ra[0].y), f2tf(ra[0].z), f2tf(ra[0].w) };
            uint4 u1 = { f2tf(ra[1].x), f2tf(ra[1].y), f2tf(ra[1].z), f2tf(ra[1].w) };
            *(uint4*)&As[m0 * APAD + kq0] = u0;
            *(uint4*)&As[m1 * APAD + kq1] = u1;
            int kb0 = fa0 >> 5, n40 = (fa0 & 31) * 4;
            int kb1 = fa1 >> 5, n41 = (fa1 & 31) * 4;
            uint4 v0 = { f2tf(rb[0].x), f2tf(rb[0].y), f2tf(rb[0].z), f2tf(rb[0].w) };
            uint4 v1 = { f2tf(rb[1].x), f2tf(rb[1].y), f2tf(rb[1].z), f2tf(rb[1].w) };
            *(uint4*)&Bs[kb0 * BPAD + n40] = v0;
            *(uint4*)&Bs[kb1 * BPAD + n41] = v1;
        }
        __syncthreads();

        // prefetch next k-tile
        if (k0 + 16 < DIMF) {
            int kn = k0 + 16;
            int m0 = fa0 >> 2, kq0 = (fa0 & 3) * 4;
            int m1 = fa1 >> 2, kq1 = (fa1 & 3) * 4;
            ra[0] = (bm + m0 < M) ? *(const float4*)(A + (size_t)(bm + m0) * DIMF + kn + kq0) : make_float4(0,0,0,0);
            ra[1] = (bm + m1 < M) ? *(const float4*)(A + (size_t)(bm + m1) * DIMF + kn + kq1) : make_float4(0,0,0,0);
            int kb0 = fa0 >> 5, n40 = (fa0 & 31) * 4;
            int kb1 = fa1 >> 5, n41 = (fa1 & 31) * 4;
            rb[0] = *(const float4*)(W + (size_t)(kn + kb0) * DIMF + bn + n40);
            rb[1] = *(const float4*)(W + (size_t)(kn + kb1) * DIMF + bn + n41);
        }

#pragma unroll
        for (int ks = 0; ks < 2; ks++) {
            const int kk = ks * 8;
            unsigned a[4][4], b[4][2];
#pragma unroll
            for (int mt = 0; mt < 4; mt++) {
                int r0 = wm + 16 * mt + gi;
                a[mt][0] = As[r0 * APAD + kk + ti];
                a[mt][1] = As[(r0 + 8) * APAD + kk + ti];
                a[mt][2] = As[r0 * APAD + kk + 4 + ti];
                a[mt][3] = As[(r0 + 8) * APAD + kk + 4 + ti];
            }
#pragma unroll
            for (int nt = 0; nt < 4; nt++) {
                int c = wn + 8 * nt + gi;
                b[nt][0] = Bs[(kk + ti) * BPAD + c];
                b[nt][1] = Bs[(kk + 4 + ti) * BPAD + c];
            }
#pragma unroll
            for (int mt = 0; mt < 4; mt++)
#pragma unroll
                for (int nt = 0; nt < 4; nt++)
                    mma8(acc[mt][nt], a[mt], b[nt]);
        }
        __syncthreads();
    }

    // epilogue + bias
#pragma unroll
    for (int mt = 0; mt < 4; mt++) {
#pragma unroll
        for (int nt = 0; nt < 4; nt++) {
            int gr0 = bm + wm + 16 * mt + gi;
            int col = bn + wn + 8 * nt + 2 * ti;
            float2 bv = *(const float2*)&bias[col];
            if (gr0 < M) {
                float2 r = { acc[mt][nt][0] + bv.x, acc[mt][nt][1] + bv.y };
                *(float2*)(out + (size_t)gr0 * DIMF + col) = r;
            }
            if (gr0 + 8 < M) {
                float2 r = { acc[mt][nt][2] + bv.x, acc[mt][nt][3] + bv.y };
                *(float2*)(out + (size_t)(gr0 + 8) * DIMF + col) = r;
            }
        }
    }
}

// ---------------------------------------------------------------------------
// RMSNorm + RoPE (unchanged from round 2, 11us)
// ---------------------------------------------------------------------------
__global__ __launch_bounds__(256) void rmsrope(
    float* __restrict__ qbuf, float* __restrict__ kbuf,
    const float* __restrict__ gq, const float* __restrict__ gk,
    const float* __restrict__ fre, const float* __restrict__ fim)
{
    const int t = blockIdx.x;
    float* row = (blockIdx.y == 0 ? qbuf : kbuf) + (size_t)t * DIMF;
    const float* g = blockIdx.y == 0 ? gq : gk;
    const int tid = threadIdx.x;

    float ss = 0.f;
#pragma unroll
    for (int u = 0; u < 6; u++) { float v = row[tid + u * 256]; ss += v * v; }
#pragma unroll
    for (int off = 16; off; off >>= 1) ss += __shfl_xor_sync(0xffffffffu, ss, off);
    __shared__ float red[8];
    if ((tid & 31) == 0) red[tid >> 5] = ss;
    __syncthreads();
    float tot = red[0] + red[1] + red[2] + red[3] + red[4] + red[5] + red[6] + red[7];
    float r = rsqrtf(tot * (1.f / 1536.f) + 1e-6f);

    const int wi = t % 52;
    const int hi = t / 52;
#pragma unroll
    for (int u = 0; u < 3; u++) {
        int p = tid + u * 256;
        int hh = p >> 6, c = p & 63;
        int d0 = hh * 128 + 2 * c;
        int frow = (c < 22) ? 3 : (c < 43) ? hi : wi;
        float cr = fre[frow * 64 + c], ci = fim[frow * 64 + c];
        float v0 = row[d0] * r * g[d0];
        float v1 = row[d0 + 1] * r * g[d0 + 1];
        row[d0]     = v0 * cr - v1 * ci;
        row[d0 + 1] = v0 * ci + v1 * cr;
    }
}

// ---------------------------------------------------------------------------
// Flash attention, tf32 tensor cores. Block = (64 queries, head), 128 threads
// (4 warps x 16 rows). Q fragments register-resident. K/V staged in padded
// smem (tf32), P staged in smem between QK and PV mma phases.
// smem: Ks[64][132] + Vs[128][68] + Ps[64][68] = 86016 B -> 2 blocks/SM.
// ---------------------------------------------------------------------------
#define KPAD 132
#define VPAD 68
#define PPAD 68
__global__ __launch_bounds__(128, 2) void attn_tf32(
    const float* __restrict__ q, const float* __restrict__ knew,
    const float* __restrict__ vnew, const float* __restrict__ ck,
    const float* __restrict__ cv, float* __restrict__ out)
{
    extern __shared__ unsigned sm[];
    unsigned* Ks = sm;                 // [kv 64][d 132]   (tf32 bits)
    unsigned* Vs = sm + 64 * KPAD;     // [d 128][kv 68]   (transposed, tf32)
    unsigned* Ps = Vs + 128 * VPAD;    // [q 64][kv 68]    (tf32)

    const int h = blockIdx.y, q0 = blockIdx.x * 64;
    const int tid = threadIdx.x, lane = tid & 31, warp = tid >> 5;
    const int gi = lane >> 2, ti = lane & 3;

    // Q fragments: warp rows 16w..16w+15, k=128 -> 16 k-tiles x 4 regs
    unsigned qf[16][4];
    {
        const float sc = 0.08838834764831845f; // 1/sqrt(128)
        int r0 = q0 + warp * 16 + gi, r1 = r0 + 8;
        const float* p0 = q + (size_t)r0 * DIMF + h * HD;
        const float* p1 = q + (size_t)r1 * DIMF + h * HD;
#pragma unroll
        for (int kt = 0; kt < 16; kt++) {
            int c = kt * 8 + ti;
            qf[kt][0] = (r0 < SEQ) ? f2tf(p0[c] * sc) : 0u;
            qf[kt][2] = (r0 < SEQ) ? f2tf(p0[c + 4] * sc) : 0u;
            qf[kt][1] = (r1 < SEQ) ? f2tf(p1[c] * sc) : 0u;
            qf[kt][3] = (r1 < SEQ) ? f2tf(p1[c + 4] * sc) : 0u;
        }
    }

    float m0v = -1e30f, m1v = -1e30f, l0 = 0.f, l1 = 0.f;
    float o[16][4];
#pragma unroll
    for (int i = 0; i < 16; i++)
#pragma unroll
        for (int c = 0; c < 4; c++) o[i][c] = 0.f;

    const int r = tid & 63, half = tid >> 6;

    for (int kv0 = 0; kv0 < LKV; kv0 += 64) {
        // --- stage K (row-major) and V (transposed) tiles, tf32 ---
        {
            int j = kv0 + r;
            bool ok = j < LKV;
            const float* ksrc; const float* vsrc;
            if (j < 1560)      { ksrc = ck + ((size_t)j * NH + h) * HD;
                                 vsrc = cv + ((size_t)j * NH + h) * HD; }
            else if (j < 3120) { ksrc = ck + ((size_t)(j + 1560) * NH + h) * HD;
                                 vsrc = cv + ((size_t)(j + 1560) * NH + h) * HD; }
            else               { ksrc = knew + (size_t)(j - 3120) * DIMF + h * HD;
                                 vsrc = vnew + (size_t)(j - 3120) * DIMF + h * HD; }
#pragma unroll
            for (int u = 0; u < 16; u++) {
                int d = half * 64 + u * 4;
                float4 k4 = ok ? *(const float4*)(ksrc + d) : make_float4(0,0,0,0);
                uint4 ku = { f2tf(k4.x), f2tf(k4.y), f2tf(k4.z), f2tf(k4.w) };
                *(uint4*)&Ks[r * KPAD + d] = ku;
                float4 v4 = ok ? *(const float4*)(vsrc + d) : make_float4(0,0,0,0);
                Vs[(d + 0) * VPAD + r] = f2tf(v4.x);
                Vs[(d + 1) * VPAD + r] = f2tf(v4.y);
                Vs[(d + 2) * VPAD + r] = f2tf(v4.z);
                Vs[(d + 3) * VPAD + r] = f2tf(v4.w);
            }
        }
        __syncthreads();

        // --- S = Q K^T : warp computes 16 x 64 ---
        float s[8][4];
#pragma unroll
        for (int nt = 0; nt < 8; nt++)
#pragma unroll
            for (int c = 0; c < 4; c++) s[nt][c] = 0.f;
#pragma unroll
        for (int kt = 0; kt < 16; kt++) {
#pragma unroll
            for (int nt = 0; nt < 8; nt++) {
                unsigned b[2];
                b[0] = Ks[(8 * nt + gi) * KPAD + 8 * kt + ti];
                b[1] = Ks[(8 * nt + gi) * KPAD + 8 * kt + 4 + ti];
                mma8(s[nt], qf[kt], b);
            }
        }

        // tail mask
        if (kv0 + 64 > LKV) {
#pragma unroll
            for (int nt = 0; nt < 8; nt++) {
                int col = kv0 + 8 * nt + 2 * ti;
                if (col >= LKV)     { s[nt][0] = -1e30f; s[nt][2] = -1e30f; }
                if (col + 1 >= LKV) { s[nt][1] = -1e30f; s[nt][3] = -1e30f; }
            }
        }

        // --- online softmax: slot0 = row gi, slot1 = row gi+8 ---
        const int pr = warp * 16 + gi;
        {
            float mx = -1e30f;
#pragma unroll
            for (int nt = 0; nt < 8; nt++) mx = fmaxf(mx, fmaxf(s[nt][0], s[nt][1]));
            mx = fmaxf(mx, __shfl_xor_sync(0xffffffffu, mx, 1));
            mx = fmaxf(mx, __shfl_xor_sync(0xffffffffu, mx, 2));
            float mn = fmaxf(m0v, mx);
            float al = __expf(m0v - mn);
            float rs = 0.f;
#pragma unroll
            for (int nt = 0; nt < 8; nt++) {
                float p0 = __expf(s[nt][0] - mn), p1 = __expf(s[nt][1] - mn);
                rs += p0 + p1;
                uint2 pu = { f2tf(p0), f2tf(p1) };
                *(uint2*)&Ps[pr * PPAD + 8 * nt + 2 * ti] = pu;
            }
            rs += __shfl_xor_sync(0xffffffffu, rs, 1);
            rs += __shfl_xor_sync(0xffffffffu, rs, 2);
            l0 = l0 * al + rs; m0v = mn;
#pragma unroll
            for (int nt = 0; nt < 16; nt++) { o[nt][0] *= al; o[nt][1] *= al; }
        }
        {
            float mx = -1e30f;
#pragma unroll
            for (int nt = 0; nt < 8; nt++) mx = fmaxf(mx, fmaxf(s[nt][2], s[nt][3]));
            mx = fmaxf(mx, __shfl_xor_sync(0xffffffffu, mx, 1));
            mx = fmaxf(mx, __shfl_xor_sync(0xffffffffu, mx, 2));
            float mn = fmaxf(m1v, mx);
            float al = __expf(m1v - mn);
            float rs = 0.f;
#pragma unroll
            for (int nt = 0; nt < 8; nt++) {
                float p0 = __expf(s[nt][2] - mn), p1 = __expf(s[nt][3] - mn);
                rs += p0 + p1;
                uint2 pu = { f2tf(p0), f2tf(p1) };
                *(uint2*)&Ps[(pr + 8) * PPAD + 8 * nt + 2 * ti] = pu;
            }
            rs += __shfl_xor_sync(0xffffffffu, rs, 1);
            rs += __shfl_xor_sync(0xffffffffu, rs, 2);
            l1 = l1 * al + rs; m1v = mn;
#pragma unroll
            for (int nt = 0; nt < 16; nt++) { o[nt][2] *= al; o[nt][3] *= al; }
        }
        __syncwarp();   // P written/read within the same warp only

        // --- O += P V : warp's 16 rows x 128 d ---
#pragma unroll
        for (int kt = 0; kt < 8; kt++) {
            unsigned a[4];
            a[0] = Ps[pr * PPAD + 8 * kt + ti];
            a[1] = Ps[(pr + 8) * PPAD + 8 * kt + ti];
            a[2] = Ps[pr * PPAD + 8 * kt + 4 + ti];
            a[3] = Ps[(pr + 8) * PPAD + 8 * kt + 4 + ti];
#pragma unroll
            for (int nt = 0; nt < 16; nt++) {
                unsigned b[2];
                b[0] = Vs[(8 * nt + gi) * VPAD + 8 * kt + ti];
                b[1] = Vs[(8 * nt + gi) * VPAD + 8 * kt + 4 + ti];
                mma8(o[nt], a, b);
            }
        }
        __syncthreads();
    }

    // epilogue
    {
        int r0 = q0 + warp * 16 + gi, r1 = r0 + 8;
        float i0 = 1.f / l0, i1 = 1.f / l1;
#pragma unroll
        for (int nt = 0; nt < 16; nt++) {
            int c = h * HD + 8 * nt + 2 * ti;
            if (r0 < SEQ) {
                float2 v = { o[nt][0] * i0, o[nt][1] * i0 };
                *(float2*)(out + (size_t)r0 * DIMF + c) = v;
            }
            if (r1 < SEQ) {
                float2 v = { o[nt][2] * i1, o[nt][3] * i1 };
                *(float2*)(out + (size_t)r1 * DIMF + c) = v;
            }
        }
    }
}

// ---------------------------------------------------------------------------
extern "C" void kernel_launch(void* const* d_in, const int* in_sizes, int n_in,
                              void* d_out, int out_size)
{
    (void)in_sizes; (void)n_in; (void)out_size;
    const float* x   = (const float*)d_in[0];
    const float* ck  = (const float*)d_in[1];
    const float* cv  = (const float*)d_in[2];
    const float* fre = (const float*)d_in[3];
    const float* fim = (const float*)d_in[4];
    const float* wq  = (const float*)d_in[5];
    const float* bq  = (const float*)d_in[6];
    const float* wk  = (const float*)d_in[7];
    const float* bk  = (const float*)d_in[8];
    const float* wv  = (const float*)d_in[9];
    const float* bv  = (const float*)d_in[10];
    const float* wo  = (const float*)d_in[11];
    const float* bo  = (const float*)d_in[12];
    const float* gq  = (const float*)d_in[13];
    const float* gk  = (const float*)d_in[14];
    float* out = (float*)d_out;

    float *q, *k, *v, *o;
    cudaGetSymbolAddress((void**)&q, g_q);
    cudaGetSymbolAddress((void**)&k, g_k);
    cudaGetSymbolAddress((void**)&v, g_v);
    cudaGetSymbolAddress((void**)&o, g_o);

    const int attn_smem = (64 * KPAD + 128 * VPAD + 64 * PPAD) * 4; // 86016
    cudaFuncSetAttribute(attn_tf32, cudaFuncAttributeMaxDynamicSharedMemorySize, attn_smem);

    dim3 gg(13, 12);
    gemm_tf32<<<gg, 256>>>(x, wq, bq, q, SEQ);
    gemm_tf32<<<gg, 256>>>(x, wk, bk, k, SEQ);
    gemm_tf32<<<gg, 256>>>(x, wv, bv, v, SEQ);
    rmsrope<<<dim3(SEQ, 2), 256>>>(q, k, gq, gk, fre, fim);
    attn_tf32<<<dim3(25, NH), 128, attn_smem>>>(q, k, v, ck, cv, o);
    gemm_tf32<<<gg, 256>>>(o, wo, bo, out, SEQ);
}